// round 1
// baseline (speedup 1.0000x reference)
#include <cuda_runtime.h>
#include <math.h>

#define NCTA 64
#define TPB  512
#define WPB  16            // warps per block
#define HID  256
#define G4   1024          // 4*HID gate rows
#define ENCL 16
#define DECL 25
#define NV   28            // vocab

// ---------------- global scratch (allocation-free) ----------------
__device__ float    g_gbuf[2][G4];   // double-buffered gate vector
__device__ unsigned g_bar_cnt;       // returns to 0 after every barrier
__device__ unsigned g_bar_gen;       // monotonic generation counter

// ---------------- grid barrier (sense-reversing, self-restoring) ----------------
__device__ __forceinline__ void grid_bar() {
    __threadfence();              // make this thread's global stores visible (writers)
    __syncthreads();              // all block stores ordered before tid0 arrives
    if (threadIdx.x == 0) {
        unsigned gen = *(volatile unsigned*)&g_bar_gen;
        if (atomicAdd(&g_bar_cnt, 1u) == NCTA - 1) {
            *(volatile unsigned*)&g_bar_cnt = 0u;
            __threadfence();
            atomicAdd(&g_bar_gen, 1u);
        } else {
            while (*(volatile unsigned*)&g_bar_gen == gen) { }
        }
        __threadfence();
    }
    __syncthreads();
}

__device__ __forceinline__ float sigf(float x) { return 1.f / (1.f + expf(-x)); }

__device__ __forceinline__ float red32(float s) {
#pragma unroll
    for (int o = 16; o > 0; o >>= 1) s += __shfl_xor_sync(0xffffffffu, s, o);
    return s;
}

__device__ __forceinline__ float dot8(float4 a0, float4 a1, float4 b0, float4 b1) {
    return a0.x*b0.x + a0.y*b0.y + a0.z*b0.z + a0.w*b0.w
         + a1.x*b1.x + a1.y*b1.y + a1.z*b1.z + a1.w*b1.w;
}

__global__ void __launch_bounds__(TPB, 1) vae_kernel(
    const int* data, const int* data_c, const int* target_c,
    const float* cond_emb, const float* enc_emb,
    const float* enc_Wih, const float* enc_Whh, const float* enc_bih, const float* enc_bhh,
    const float* hmu_W, const float* hmu_b, const float* cmu_W, const float* cmu_b,
    const float* fc1_W, const float* fc1_b, const float* fc2_W, const float* fc2_b,
    const float* dec_emb, const float* dec_Wih, const float* dec_Whh,
    const float* dec_bih, const float* dec_bhh,
    const float* out_W, const float* out_b,
    float* out, int out_size)
{
    __shared__ __align__(16) float hsh[HID];
    __shared__ __align__(16) float csh[HID];
    __shared__ __align__(16) float ow_sh[NV * HID];      // 28 KB: out_W cache
    __shared__ float ob_sh[NV];
    __shared__ float tab_sh[NV * WPB];                   // dec input-proj table [tok][warp]
    __shared__ float pre_sh[ENCL * WPB];                 // enc input-proj [t][warp]
    __shared__ float lsh[NV];
    __shared__ float cat_h[40], cat_c[40];
    __shared__ int   tok_sh;

    const int tid  = threadIdx.x;
    const int w    = tid >> 5;
    const int lane = tid & 31;
    const int b    = blockIdx.x;
    const int row  = b * WPB + w;                        // gate row 0..1023

    // ---- recurrent weight rows -> registers (16 regs/lane) ----
    const float4* pe = (const float4*)(enc_Whh + row * HID);
    float4 we0 = pe[lane * 2], we1 = pe[lane * 2 + 1];
    const float4* pd = (const float4*)(dec_Whh + row * HID);
    float4 wd0 = pd[lane * 2], wd1 = pd[lane * 2 + 1];

    // ---- out_W / out_b -> smem ----
    for (int i = tid; i < NV * HID / 4; i += TPB)
        ((float4*)ow_sh)[i] = ((const float4*)out_W)[i];
    if (tid < NV) ob_sh[tid] = out_b[tid];

    // ---- precompute encoder input projections (per-warp row) ----
    {
        const float4* q = (const float4*)(enc_Wih + row * HID);
        float4 a0 = q[lane * 2], a1 = q[lane * 2 + 1];
        float bias = enc_bih[row] + enc_bhh[row];
#pragma unroll 1
        for (int t = 0; t < ENCL; t++) {
            const float4* x = (const float4*)(enc_emb + data[t] * HID);
            float4 x0 = x[lane * 2], x1 = x[lane * 2 + 1];
            float s = red32(dot8(a0, a1, x0, x1));
            if (lane == 0) pre_sh[t * WPB + w] = s + bias;
        }
    }
    // ---- precompute decoder token table (all 28 tokens) ----
    {
        const float4* q = (const float4*)(dec_Wih + row * HID);
        float4 a0 = q[lane * 2], a1 = q[lane * 2 + 1];
        float bias = dec_bih[row] + dec_bhh[row];
#pragma unroll 1
        for (int tk = 0; tk < NV; tk++) {
            const float4* x = (const float4*)(dec_emb + tk * HID);
            float4 x0 = x[lane * 2], x1 = x[lane * 2 + 1];
            x0.x = fmaxf(x0.x, 0.f); x0.y = fmaxf(x0.y, 0.f);
            x0.z = fmaxf(x0.z, 0.f); x0.w = fmaxf(x0.w, 0.f);
            x1.x = fmaxf(x1.x, 0.f); x1.y = fmaxf(x1.y, 0.f);
            x1.z = fmaxf(x1.z, 0.f); x1.w = fmaxf(x1.w, 0.f);
            float s = red32(dot8(a0, a1, x0, x1));
            if (lane == 0) tab_sh[tk * WPB + w] = s + bias;
        }
    }

    // ---- h0 / c0 : zeros(248) ++ cond_emb[data_c] ----
    const int dcid = data_c[0], tcid = target_c[0];
    if (tid < HID) {
        float v = (tid >= HID - 8) ? cond_emb[dcid * 8 + (tid - (HID - 8))] : 0.f;
        hsh[tid] = v; csh[tid] = v;
    }
    __syncthreads();

    // ================= encoder: 16 sequential steps =================
#pragma unroll 1
    for (int t = 0; t < ENCL; t++) {
        const float4* hv = (const float4*)hsh + lane * 2;
        float4 h0v = hv[0], h1v = hv[1];
        float s = red32(dot8(we0, we1, h0v, h1v));
        if (lane == 0) g_gbuf[t & 1][row] = s + pre_sh[t * WPB + w];
        grid_bar();
        if (tid < HID) {
            float gi = __ldcg(&g_gbuf[t & 1][tid]);
            float gf = __ldcg(&g_gbuf[t & 1][HID + tid]);
            float gg = __ldcg(&g_gbuf[t & 1][2 * HID + tid]);
            float go = __ldcg(&g_gbuf[t & 1][3 * HID + tid]);
            float c = sigf(gf) * csh[tid] + sigf(gi) * tanhf(gg);
            float h = sigf(go) * tanhf(c);
            csh[tid] = c; hsh[tid] = h;
        }
        __syncthreads();
    }

    // ================= latent heads + decoder init (redundant per CTA) =================
    {
        const float4* hv = (const float4*)hsh + lane * 2;
        float4 h0v = hv[0], h1v = hv[1];
        const float4* cv = (const float4*)csh + lane * 2;
        float4 c0v = cv[0], c1v = cv[1];
#pragma unroll
        for (int half = 0; half < 2; half++) {
            int rr = w + half * 16;                      // 0..31
            const float4* q = (const float4*)(hmu_W + rr * HID);
            float4 a0 = q[lane * 2], a1 = q[lane * 2 + 1];
            float s = red32(dot8(a0, a1, h0v, h1v));
            if (lane == 0) cat_h[rr] = s + hmu_b[rr];
            q = (const float4*)(cmu_W + rr * HID);
            a0 = q[lane * 2]; a1 = q[lane * 2 + 1];
            s = red32(dot8(a0, a1, c0v, c1v));
            if (lane == 0) cat_c[rr] = s + cmu_b[rr];
        }
    }
    if (tid < 8) {
        float v = cond_emb[tcid * 8 + tid];
        cat_h[32 + tid] = v; cat_c[32 + tid] = v;
    }
    __syncthreads();
    float newv;
    if (tid < HID) {
        float s = fc1_b[tid];
        const float* wrow = fc1_W + tid * 40;
#pragma unroll
        for (int k = 0; k < 40; k++) s += cat_h[k] * wrow[k];
        newv = s;
    } else {
        int j = tid - HID;
        float s = fc2_b[j];
        const float* wrow = fc2_W + j * 40;
#pragma unroll
        for (int k = 0; k < 40; k++) s += cat_c[k] * wrow[k];
        newv = s;
    }
    __syncthreads();
    if (tid < HID) hsh[tid] = newv; else csh[tid - HID] = newv;
    if (tid == 0) tok_sh = 0;                            // SOS
    __syncthreads();

    // ================= decoder: 25 sequential steps =================
#pragma unroll 1
    for (int s = 0; s < DECL; s++) {
        int tok = tok_sh;
        float pre = tab_sh[tok * WPB + w];
        const float4* hv = (const float4*)hsh + lane * 2;
        float4 h0v = hv[0], h1v = hv[1];
        float acc = red32(dot8(wd0, wd1, h0v, h1v));
        if (lane == 0) g_gbuf[s & 1][row] = acc + pre;
        grid_bar();
        if (tid < HID) {
            float gi = __ldcg(&g_gbuf[s & 1][tid]);
            float gf = __ldcg(&g_gbuf[s & 1][HID + tid]);
            float gg = __ldcg(&g_gbuf[s & 1][2 * HID + tid]);
            float go = __ldcg(&g_gbuf[s & 1][3 * HID + tid]);
            float c = sigf(gf) * csh[tid] + sigf(gi) * tanhf(gg);
            float h = sigf(go) * tanhf(c);
            csh[tid] = c; hsh[tid] = h;
        }
        __syncthreads();
        // logits = h @ out_W.T + out_b   (redundant per CTA, smem weights)
        if (w < 14) {
            const float4* h2 = (const float4*)hsh + lane * 2;
            float4 x0 = h2[0], x1 = h2[1];
#pragma unroll
            for (int half = 0; half < 2; half++) {
                int rr = w + half * 14;                  // 0..27
                const float4* q = (const float4*)(ow_sh + rr * HID) + lane * 2;
                float4 a0 = q[0], a1 = q[1];
                float sl = red32(dot8(a0, a1, x0, x1));
                if (lane == 0) lsh[rr] = sl + ob_sh[rr];
            }
        }
        __syncthreads();
        if (tid == 0) {
            int best = 0; float bv = lsh[0];
#pragma unroll
            for (int k = 1; k < NV; k++) if (lsh[k] > bv) { bv = lsh[k]; best = k; }
            tok_sh = best;
            if (b == 0 && out_size >= NV * DECL + DECL) out[NV * DECL + s] = (float)best;
        }
        if (b == 0 && tid < NV) out[s * NV + tid] = lsh[tid];
        __syncthreads();
    }
}

extern "C" void kernel_launch(void* const* d_in, const int* in_sizes, int n_in,
                              void* d_out, int out_size) {
    (void)in_sizes; (void)n_in;
    const int*   data     = (const int*)  d_in[0];
    const int*   data_c   = (const int*)  d_in[1];
    const int*   target_c = (const int*)  d_in[2];
    const float* cond_emb = (const float*)d_in[3];
    const float* enc_emb  = (const float*)d_in[4];
    const float* enc_Wih  = (const float*)d_in[5];
    const float* enc_Whh  = (const float*)d_in[6];
    const float* enc_bih  = (const float*)d_in[7];
    const float* enc_bhh  = (const float*)d_in[8];
    const float* hmu_W    = (const float*)d_in[9];
    const float* hmu_b    = (const float*)d_in[10];
    const float* cmu_W    = (const float*)d_in[11];
    const float* cmu_b    = (const float*)d_in[12];
    const float* fc1_W    = (const float*)d_in[13];
    const float* fc1_b    = (const float*)d_in[14];
    const float* fc2_W    = (const float*)d_in[15];
    const float* fc2_b    = (const float*)d_in[16];
    const float* dec_emb  = (const float*)d_in[17];
    const float* dec_Wih  = (const float*)d_in[18];
    const float* dec_Whh  = (const float*)d_in[19];
    const float* dec_bih  = (const float*)d_in[20];
    const float* dec_bhh  = (const float*)d_in[21];
    const float* out_W    = (const float*)d_in[22];
    const float* out_b    = (const float*)d_in[23];

    vae_kernel<<<NCTA, TPB>>>(data, data_c, target_c, cond_emb, enc_emb,
                              enc_Wih, enc_Whh, enc_bih, enc_bhh,
                              hmu_W, hmu_b, cmu_W, cmu_b,
                              fc1_W, fc1_b, fc2_W, fc2_b,
                              dec_emb, dec_Wih, dec_Whh, dec_bih, dec_bhh,
                              out_W, out_b,
                              (float*)d_out, out_size);
}

// round 2
// speedup vs baseline: 1.7141x; 1.7141x over previous
#include <cuda_runtime.h>
#include <math.h>
#include <stdint.h>

#define CS   8              // cluster size (CTAs) = SMs used
#define TPB  512
#define WPB  16             // warps per CTA
#define HID  256
#define G4   1024           // 4*HID gate rows
#define ENCL 16
#define DECL 25
#define NV   28             // vocab
#define RPC  128            // gate rows per CTA

typedef unsigned long long ull;

// ---------------- dynamic smem layout (bytes) ----------------
#define OFF_GBUF   0                        // 2*1024*4 = 8192   double-buffered gates (full copy per CTA)
#define OFF_H      (OFF_GBUF + 8192)        // 1024
#define OFF_C      (OFF_H + 1024)           // 1024
#define OFF_OW     (OFF_C + 1024)           // 28*256*4 = 28672  out_W cache
#define OFF_OB     (OFF_OW + 28672)         // 128
#define OFF_PRE    (OFF_OB + 128)           // 16*128*4 = 8192   enc input projections
#define OFF_TAB    (OFF_PRE + 8192)         // 28*128*4 = 14336  dec token table
#define OFF_XS     (OFF_TAB + 14336)        // 28*256*4 = 28672  staging for emb rows
#define OFF_LSH    (OFF_XS + 28672)         // 128               logits
#define OFF_CATH   (OFF_LSH + 128)          // 192
#define OFF_CATC   (OFF_CATH + 192)         // 192
#define OFF_TOK    (OFF_CATC + 192)         // 16
#define SMEM_TOTAL (OFF_TOK + 16)

// ---------------- PTX helpers ----------------
__device__ __forceinline__ uint32_t smem_u32(const void* p) {
    uint32_t a;
    asm("{ .reg .u64 t; cvta.to.shared.u64 t, %1; cvt.u32.u64 %0, t; }" : "=r"(a) : "l"(p));
    return a;
}
__device__ __forceinline__ uint32_t mapa_u32(uint32_t a, uint32_t rank) {
    uint32_t r;
    asm("mapa.shared::cluster.u32 %0, %1, %2;" : "=r"(r) : "r"(a), "r"(rank));
    return r;
}
__device__ __forceinline__ void st_cluster_f32(uint32_t addr, float v) {
    asm volatile("st.shared::cluster.u32 [%0], %1;" :: "r"(addr), "r"(__float_as_uint(v)) : "memory");
}
__device__ __forceinline__ void cluster_bar() {
    asm volatile("barrier.cluster.arrive.aligned;" ::: "memory");
    asm volatile("barrier.cluster.wait.aligned;" ::: "memory");
}
__device__ __forceinline__ void ffma2(ull &acc, ull a, ull b) {
    asm("fma.rn.f32x2 %0, %1, %2, %0;" : "+l"(acc) : "l"(a), "l"(b));
}
__device__ __forceinline__ float ups(ull a) {       // unpack f32x2 accumulator, sum halves
    float lo, hi;
    asm("mov.b64 {%0,%1}, %2;" : "=f"(lo), "=f"(hi) : "l"(a));
    return lo + hi;
}
__device__ __forceinline__ float sigf(float x) {
    return __fdividef(1.f, 1.f + __expf(-x));
}
__device__ __forceinline__ float tanhfast(float x) {
    float t = __expf(-2.f * fabsf(x));
    float r = __fdividef(1.f - t, 1.f + t);
    return copysignf(r, x);
}
__device__ __forceinline__ float red32(float s) {
#pragma unroll
    for (int o = 16; o > 0; o >>= 1) s += __shfl_xor_sync(0xffffffffu, s, o);
    return s;
}
__device__ __forceinline__ float dot8(float4 a0, float4 a1, float4 b0, float4 b1) {
    return a0.x*b0.x + a0.y*b0.y + a0.z*b0.z + a0.w*b0.w
         + a1.x*b1.x + a1.y*b1.y + a1.z*b1.z + a1.w*b1.w;
}

// load 2 gate rows (RA, RB), slice s8, rotation-swizzled into reg arrays
__device__ __forceinline__ void load_wrows(const float* W, int RA, int RB, int s8,
                                           ull* wA, ull* wB) {
#pragma unroll
    for (int kk = 0; kk < 8; kk++) {
        int k = (kk + s8) & 7;                                   // rotated chunk order
        ulonglong2 a = *(const ulonglong2*)(W + RA * HID + s8 * 32 + k * 4);
        ulonglong2 b = *(const ulonglong2*)(W + RB * HID + s8 * 32 + k * 4);
        wA[2*kk] = a.x; wA[2*kk+1] = a.y;
        wB[2*kk] = b.x; wB[2*kk+1] = b.y;
    }
}

// dual 64-elem packed dot against smem vector `v` (slice s8, rotated), reduced over 8 lanes
__device__ __forceinline__ void dual_dot(const float* v, int s8,
                                         const ull* wA, const ull* wB,
                                         float &sA, float &sB) {
    ull aA = 0ull, aB = 0ull;
#pragma unroll
    for (int kk = 0; kk < 8; kk++) {
        int k = (kk + s8) & 7;
        ulonglong2 x = *(const ulonglong2*)(v + s8 * 32 + k * 4);
        ffma2(aA, wA[2*kk], x.x); ffma2(aA, wA[2*kk+1], x.y);
        ffma2(aB, wB[2*kk], x.x); ffma2(aB, wB[2*kk+1], x.y);
    }
    float fA = ups(aA), fB = ups(aB);
#pragma unroll
    for (int o = 1; o < 8; o <<= 1) {
        fA += __shfl_xor_sync(0xffffffffu, fA, o);
        fB += __shfl_xor_sync(0xffffffffu, fB, o);
    }
    sA = fA; sB = fB;
}

__global__ void __launch_bounds__(TPB, 1) __cluster_dims__(CS, 1, 1) vae_kernel(
    const int* data, const int* data_c, const int* target_c,
    const float* cond_emb, const float* enc_emb,
    const float* enc_Wih, const float* enc_Whh, const float* enc_bih, const float* enc_bhh,
    const float* hmu_W, const float* hmu_b, const float* cmu_W, const float* cmu_b,
    const float* fc1_W, const float* fc1_b, const float* fc2_W, const float* fc2_b,
    const float* dec_emb, const float* dec_Wih, const float* dec_Whh,
    const float* dec_bih, const float* dec_bhh,
    const float* out_W, const float* out_b,
    float* out, int out_size)
{
    extern __shared__ __align__(16) char dyn[];
    float* gbuf  = (float*)(dyn + OFF_GBUF);
    float* hsh   = (float*)(dyn + OFF_H);
    float* csh   = (float*)(dyn + OFF_C);
    float* ow_sh = (float*)(dyn + OFF_OW);
    float* ob_sh = (float*)(dyn + OFF_OB);
    float* pre_sh= (float*)(dyn + OFF_PRE);
    float* tab_sh= (float*)(dyn + OFF_TAB);
    float* xs_sh = (float*)(dyn + OFF_XS);
    float* lsh   = (float*)(dyn + OFF_LSH);
    float* cat_h = (float*)(dyn + OFF_CATH);
    float* cat_c = (float*)(dyn + OFF_CATC);
    int*   tok_sh= (int*)  (dyn + OFF_TOK);

    const int tid  = threadIdx.x;
    const int w    = tid >> 5;
    const int lane = tid & 31;
    const int s8   = lane & 7;       // element-slice id == destination cluster rank
    const int q    = lane >> 3;      // sub-row 0..3
    const int b    = blockIdx.x;     // == cluster rank (one cluster)
    const int lrA  = w * 8 + q;      // local gate rows (this CTA owns 128)
    const int lrB  = lrA + 4;
    const int RA   = b * RPC + lrA;  // global gate rows 0..1023
    const int RB   = b * RPC + lrB;

    const uint32_t gbase = smem_u32(gbuf);
    const uint32_t rbase = mapa_u32(gbase, (uint32_t)s8);  // my write target: CTA rank s8's gbuf

    // ---- out_W / out_b -> smem ----
    for (int i = tid; i < NV * HID / 4; i += TPB)
        ((float4*)ow_sh)[i] = ((const float4*)out_W)[i];
    if (tid < NV) ob_sh[tid] = out_b[tid];

    // ---- stage encoder inputs xs[t] = enc_emb[data[t]] ----
    for (int i = tid; i < ENCL * 64; i += TPB) {
        int t = i >> 6, c4 = i & 63;
        ((float4*)xs_sh)[i] = ((const float4*)(enc_emb + data[t] * HID))[c4];
    }
    __syncthreads();

    // ---- encoder input projections -> pre_sh[t][lr] ----
    {
        ull wiA[16], wiB[16];
        load_wrows(enc_Wih, RA, RB, s8, wiA, wiB);
        float biasA = enc_bih[RA] + enc_bhh[RA];
        float biasB = enc_bih[RB] + enc_bhh[RB];
#pragma unroll 1
        for (int t = 0; t < ENCL; t++) {
            float sA, sB;
            dual_dot(xs_sh + t * HID, s8, wiA, wiB, sA, sB);
            if (s8 == 0) {
                pre_sh[t * RPC + lrA] = sA + biasA;
                pre_sh[t * RPC + lrB] = sB + biasB;
            }
        }
    }
    __syncthreads();

    // ---- stage decoder inputs xs[tok] = relu(dec_emb[tok]) ----
    for (int i = tid; i < NV * 64; i += TPB) {
        int tk = i >> 6, c4 = i & 63;
        float4 v = ((const float4*)(dec_emb + tk * HID))[c4];
        v.x = fmaxf(v.x, 0.f); v.y = fmaxf(v.y, 0.f);
        v.z = fmaxf(v.z, 0.f); v.w = fmaxf(v.w, 0.f);
        ((float4*)xs_sh)[i] = v;
    }
    __syncthreads();

    // ---- decoder token table -> tab_sh[tok][lr] ----
    {
        ull wiA[16], wiB[16];
        load_wrows(dec_Wih, RA, RB, s8, wiA, wiB);
        float biasA = dec_bih[RA] + dec_bhh[RA];
        float biasB = dec_bih[RB] + dec_bhh[RB];
#pragma unroll 1
        for (int tk = 0; tk < NV; tk++) {
            float sA, sB;
            dual_dot(xs_sh + tk * HID, s8, wiA, wiB, sA, sB);
            if (s8 == 0) {
                tab_sh[tk * RPC + lrA] = sA + biasA;
                tab_sh[tk * RPC + lrB] = sB + biasB;
            }
        }
    }

    // ---- h0 / c0 : zeros(248) ++ cond_emb[data_c] ----
    const int dcid = data_c[0], tcid = target_c[0];
    if (tid < HID) {
        float v = (tid >= HID - 8) ? cond_emb[dcid * 8 + (tid - (HID - 8))] : 0.f;
        hsh[tid] = v; csh[tid] = v;
    }

    // ---- encoder recurrent weights -> regs ----
    ull eA[16], eB[16];
    load_wrows(enc_Whh, RA, RB, s8, eA, eB);
    __syncthreads();

    // ================= encoder: 16 sequential steps =================
#pragma unroll 1
    for (int t = 0; t < ENCL; t++) {
        float sA, sB;
        dual_dot(hsh, s8, eA, eB, sA, sB);
        float gA = sA + pre_sh[t * RPC + lrA];
        float gB = sB + pre_sh[t * RPC + lrB];
        uint32_t boff = (uint32_t)((t & 1) * G4) * 4u;
        st_cluster_f32(rbase + boff + RA * 4, gA);
        st_cluster_f32(rbase + boff + RB * 4, gB);
        cluster_bar();
        if (tid < HID) {
            const float* gb = gbuf + (t & 1) * G4;
            float gi = gb[tid], gf = gb[HID + tid], gg = gb[2*HID + tid], go = gb[3*HID + tid];
            float c = sigf(gf) * csh[tid] + sigf(gi) * tanhfast(gg);
            float h = sigf(go) * tanhfast(c);
            csh[tid] = c; hsh[tid] = h;
        }
        __syncthreads();
    }

    // ================= latent heads + decoder init (redundant per CTA) =================
    {
        const float4* hv = (const float4*)hsh + lane * 2;
        float4 h0v = hv[0], h1v = hv[1];
        const float4* cv = (const float4*)csh + lane * 2;
        float4 c0v = cv[0], c1v = cv[1];
#pragma unroll
        for (int half = 0; half < 2; half++) {
            int rr = w + half * 16;                      // 0..31
            const float4* p = (const float4*)(hmu_W + rr * HID);
            float4 a0 = p[lane * 2], a1 = p[lane * 2 + 1];
            float s = red32(dot8(a0, a1, h0v, h1v));
            if (lane == 0) cat_h[rr] = s + hmu_b[rr];
            p = (const float4*)(cmu_W + rr * HID);
            a0 = p[lane * 2]; a1 = p[lane * 2 + 1];
            s = red32(dot8(a0, a1, c0v, c1v));
            if (lane == 0) cat_c[rr] = s + cmu_b[rr];
        }
    }
    if (tid < 8) {
        float v = cond_emb[tcid * 8 + tid];
        cat_h[32 + tid] = v; cat_c[32 + tid] = v;
    }
    __syncthreads();
    float newv;
    if (tid < HID) {
        float s = fc1_b[tid];
        const float* wr = fc1_W + tid * 40;
#pragma unroll
        for (int k = 0; k < 40; k++) s += cat_h[k] * wr[k];
        newv = s;
    } else {
        int j = tid - HID;
        float s = fc2_b[j];
        const float* wr = fc2_W + j * 40;
#pragma unroll
        for (int k = 0; k < 40; k++) s += cat_c[k] * wr[k];
        newv = s;
    }
    __syncthreads();
    if (tid < HID) hsh[tid] = newv; else csh[tid - HID] = newv;
    if (tid == 0) *tok_sh = 0;                           // SOS
    // decoder recurrent weights -> regs (enc weights dead now)
    ull dA[16], dB[16];
    load_wrows(dec_Whh, RA, RB, s8, dA, dB);
    __syncthreads();

    // ================= decoder: 25 sequential steps =================
#pragma unroll 1
    for (int s = 0; s < DECL; s++) {
        int tok = *tok_sh;
        float preA = tab_sh[tok * RPC + lrA];
        float preB = tab_sh[tok * RPC + lrB];
        float sA, sB;
        dual_dot(hsh, s8, dA, dB, sA, sB);
        float gA = sA + preA;
        float gB = sB + preB;
        uint32_t boff = (uint32_t)((s & 1) * G4) * 4u;
        st_cluster_f32(rbase + boff + RA * 4, gA);
        st_cluster_f32(rbase + boff + RB * 4, gB);
        cluster_bar();
        if (tid < HID) {
            const float* gb = gbuf + (s & 1) * G4;
            float gi = gb[tid], gf = gb[HID + tid], gg = gb[2*HID + tid], go = gb[3*HID + tid];
            float c = sigf(gf) * csh[tid] + sigf(gi) * tanhfast(gg);
            float h = sigf(go) * tanhfast(c);
            csh[tid] = c; hsh[tid] = h;
        }
        __syncthreads();
        // logits = h @ out_W.T + out_b (redundant per CTA, smem weights)
        if (w < 14) {
            const float4* h2 = (const float4*)hsh + lane * 2;
            float4 x0 = h2[0], x1 = h2[1];
#pragma unroll
            for (int half = 0; half < 2; half++) {
                int rr = w + half * 14;                  // 0..27
                const float4* p = (const float4*)(ow_sh + rr * HID) + lane * 2;
                float4 a0 = p[0], a1 = p[1];
                float sl = red32(dot8(a0, a1, x0, x1));
                if (lane == 0) lsh[rr] = sl + ob_sh[rr];
            }
        }
        __syncthreads();
        // warp-parallel argmax (first-max tie rule, matching jnp.argmax)
        if (w == 0) {
            float v = (lane < NV) ? lsh[lane] : -3.4e38f;
            int idx = lane;
#pragma unroll
            for (int o = 16; o > 0; o >>= 1) {
                float ov = __shfl_xor_sync(0xffffffffu, v, o);
                int   oi = __shfl_xor_sync(0xffffffffu, idx, o);
                if (ov > v || (ov == v && oi < idx)) { v = ov; idx = oi; }
            }
            if (lane == 0) {
                *tok_sh = idx;
                if (b == 0 && out_size >= NV * DECL + DECL) out[NV * DECL + s] = (float)idx;
            }
        }
        if (b == 0 && tid < NV) out[s * NV + tid] = lsh[tid];
        __syncthreads();
    }
}

extern "C" void kernel_launch(void* const* d_in, const int* in_sizes, int n_in,
                              void* d_out, int out_size) {
    (void)in_sizes; (void)n_in;
    const int*   data     = (const int*)  d_in[0];
    const int*   data_c   = (const int*)  d_in[1];
    const int*   target_c = (const int*)  d_in[2];
    const float* cond_emb = (const float*)d_in[3];
    const float* enc_emb  = (const float*)d_in[4];
    const float* enc_Wih  = (const float*)d_in[5];
    const float* enc_Whh  = (const float*)d_in[6];
    const float* enc_bih  = (const float*)d_in[7];
    const float* enc_bhh  = (const float*)d_in[8];
    const float* hmu_W    = (const float*)d_in[9];
    const float* hmu_b    = (const float*)d_in[10];
    const float* cmu_W    = (const float*)d_in[11];
    const float* cmu_b    = (const float*)d_in[12];
    const float* fc1_W    = (const float*)d_in[13];
    const float* fc1_b    = (const float*)d_in[14];
    const float* fc2_W    = (const float*)d_in[15];
    const float* fc2_b    = (const float*)d_in[16];
    const float* dec_emb  = (const float*)d_in[17];
    const float* dec_Wih  = (const float*)d_in[18];
    const float* dec_Whh  = (const float*)d_in[19];
    const float* dec_bih  = (const float*)d_in[20];
    const float* dec_bhh  = (const float*)d_in[21];
    const float* out_W    = (const float*)d_in[22];
    const float* out_b    = (const float*)d_in[23];

    cudaFuncSetAttribute(vae_kernel, cudaFuncAttributeMaxDynamicSharedMemorySize, SMEM_TOTAL);

    vae_kernel<<<CS, TPB, SMEM_TOTAL>>>(data, data_c, target_c, cond_emb, enc_emb,
                                        enc_Wih, enc_Whh, enc_bih, enc_bhh,
                                        hmu_W, hmu_b, cmu_W, cmu_b,
                                        fc1_W, fc1_b, fc2_W, fc2_b,
                                        dec_emb, dec_Wih, dec_Whh, dec_bih, dec_bhh,
                                        out_W, out_b,
                                        (float*)d_out, out_size);
}

// round 3
// speedup vs baseline: 2.0518x; 1.1970x over previous
#include <cuda_runtime.h>
#include <math.h>
#include <stdint.h>

#define CS   8              // cluster size
#define TPB  512
#define HID  256
#define ENCL 16
#define DECL 25
#define NV   28
#define RPC  128            // gate rows per CTA
#define HPC  32             // hidden units per CTA

typedef unsigned long long ull;

// precomputed input-projection tables (built by table_kernel)
__device__ float g_pre[ENCL * 1024];   // enc: x_t @ Wih.T + bih + bhh
__device__ float g_tab[NV * 1024];     // dec: relu(emb[tok]) @ Wih.T + bih + bhh

// ---------------- smem layout of main kernel (floats) ----------------
#define O_H     0           // h[2][256]
#define O_GSH   512         // gates [128]
#define O_CF    640         // cfull [256]
#define O_PRE   896         // pre   [16*128]
#define O_TAB   2944        // tab   [28*128]
#define O_OW    6528        // out_W [28*256]
#define O_OB    13696       // out_b [28] -> pad 32
#define O_LSH   13728       // logits [28] -> pad 32
#define O_CATH  13760       // [40]
#define O_CATC  13800       // [40]
#define SMEM_FLOATS 13840
#define SMEM_BYTES  (SMEM_FLOATS * 4)

// ---------------- PTX helpers ----------------
__device__ __forceinline__ uint32_t smem_u32(const void* p) {
    uint32_t a;
    asm("{ .reg .u64 t; cvta.to.shared.u64 t, %1; cvt.u32.u64 %0, t; }" : "=r"(a) : "l"(p));
    return a;
}
__device__ __forceinline__ uint32_t mapa_u32(uint32_t a, uint32_t rank) {
    uint32_t r;
    asm("mapa.shared::cluster.u32 %0, %1, %2;" : "=r"(r) : "r"(a), "r"(rank));
    return r;
}
__device__ __forceinline__ void st_cluster_f32(uint32_t addr, float v) {
    asm volatile("st.shared::cluster.u32 [%0], %1;" :: "r"(addr), "r"(__float_as_uint(v)) : "memory");
}
__device__ __forceinline__ void cluster_bar() {
    asm volatile("barrier.cluster.arrive.aligned;" ::: "memory");
    asm volatile("barrier.cluster.wait.aligned;" ::: "memory");
}
__device__ __forceinline__ void ffma2(ull &acc, ull a, ull b) {
    asm("fma.rn.f32x2 %0, %1, %2, %0;" : "+l"(acc) : "l"(a), "l"(b));
}
__device__ __forceinline__ float ups(ull a) {
    float lo, hi;
    asm("mov.b64 {%0,%1}, %2;" : "=f"(lo), "=f"(hi) : "l"(a));
    return lo + hi;
}
__device__ __forceinline__ float sigf(float x) {
    return __fdividef(1.f, 1.f + __expf(-x));
}
__device__ __forceinline__ float tanhfast(float x) {
    float t = __expf(-2.f * fabsf(x));
    float r = __fdividef(1.f - t, 1.f + t);
    return copysignf(r, x);
}
__device__ __forceinline__ float red32(float s) {
#pragma unroll
    for (int o = 16; o > 0; o >>= 1) s += __shfl_xor_sync(0xffffffffu, s, o);
    return s;
}
__device__ __forceinline__ float dot8(float4 a0, float4 a1, float4 b0, float4 b1) {
    return a0.x*b0.x + a0.y*b0.y + a0.z*b0.z + a0.w*b0.w
         + a1.x*b1.x + a1.y*b1.y + a1.z*b1.z + a1.w*b1.w;
}
// local gate row -> global gate row (gate-major, CTA b owns hidden [32b,32b+32))
__device__ __forceinline__ int R_of(int lr, int b) {
    return (lr >> 5) * HID + b * HPC + (lr & 31);
}

// load 2 gate rows (RA, RB), slice s8, rotation-swizzled
__device__ __forceinline__ void load_wrows(const float* W, int RA, int RB, int s8,
                                           ull* wA, ull* wB) {
#pragma unroll
    for (int kk = 0; kk < 8; kk++) {
        int k = (kk + s8) & 7;
        ulonglong2 a = *(const ulonglong2*)(W + RA * HID + s8 * 32 + k * 4);
        ulonglong2 b = *(const ulonglong2*)(W + RB * HID + s8 * 32 + k * 4);
        wA[2*kk] = a.x; wA[2*kk+1] = a.y;
        wB[2*kk] = b.x; wB[2*kk+1] = b.y;
    }
}
// dual 64-elem packed dot vs smem vec, reduced over 8 lanes (all lanes get sum)
__device__ __forceinline__ void dual_dot(const float* v, int s8,
                                         const ull* wA, const ull* wB,
                                         float &sA, float &sB) {
    ull aA = 0ull, aB = 0ull;
#pragma unroll
    for (int kk = 0; kk < 8; kk++) {
        int k = (kk + s8) & 7;
        ulonglong2 x = *(const ulonglong2*)(v + s8 * 32 + k * 4);
        ffma2(aA, wA[2*kk], x.x); ffma2(aA, wA[2*kk+1], x.y);
        ffma2(aB, wB[2*kk], x.x); ffma2(aB, wB[2*kk+1], x.y);
    }
    float fA = ups(aA), fB = ups(aB);
#pragma unroll
    for (int o = 1; o < 8; o <<= 1) {
        fA += __shfl_xor_sync(0xffffffffu, fA, o);
        fB += __shfl_xor_sync(0xffffffffu, fB, o);
    }
    sA = fA; sB = fB;
}

// ================= kernel 1: build projection tables on many SMs =================
__global__ void __launch_bounds__(256) table_kernel(
    const int* data,
    const float* enc_Wih, const float* enc_bih, const float* enc_bhh, const float* enc_emb,
    const float* dec_Wih, const float* dec_bih, const float* dec_bhh, const float* dec_emb)
{
    const int tid  = threadIdx.x;
    const int w    = tid >> 5;          // 0..7
    const int lane = tid & 31;
    const int g    = blockIdx.x;        // 0..255
    const int m    = w >> 2;            // 0 = enc, 1 = dec
    const int R    = g * 4 + (w & 3);   // gate row 0..1023

    if (m == 0) {
        const float4* p = (const float4*)(enc_Wih + R * HID);
        float4 a0 = p[lane * 2], a1 = p[lane * 2 + 1];
        float bias = enc_bih[R] + enc_bhh[R];
#pragma unroll
        for (int t = 0; t < ENCL; t++) {
            const float4* x = (const float4*)(enc_emb + data[t] * HID);
            float4 x0 = x[lane * 2], x1 = x[lane * 2 + 1];
            float s = red32(dot8(a0, a1, x0, x1));
            if (lane == 0) g_pre[t * 1024 + R] = s + bias;
        }
    } else {
        const float4* p = (const float4*)(dec_Wih + R * HID);
        float4 a0 = p[lane * 2], a1 = p[lane * 2 + 1];
        float bias = dec_bih[R] + dec_bhh[R];
#pragma unroll
        for (int tk = 0; tk < NV; tk++) {
            const float4* x = (const float4*)(dec_emb + tk * HID);
            float4 x0 = x[lane * 2], x1 = x[lane * 2 + 1];
            x0.x = fmaxf(x0.x, 0.f); x0.y = fmaxf(x0.y, 0.f);
            x0.z = fmaxf(x0.z, 0.f); x0.w = fmaxf(x0.w, 0.f);
            x1.x = fmaxf(x1.x, 0.f); x1.y = fmaxf(x1.y, 0.f);
            x1.z = fmaxf(x1.z, 0.f); x1.w = fmaxf(x1.w, 0.f);
            float s = red32(dot8(a0, a1, x0, x1));
            if (lane == 0) g_tab[tk * 1024 + R] = s + bias;
        }
    }
}

// ================= kernel 2: sequential LSTM on an 8-CTA cluster =================
__global__ void __launch_bounds__(TPB, 1) __cluster_dims__(CS, 1, 1) vae_kernel(
    const int* data_c, const int* target_c, const float* cond_emb,
    const float* enc_Whh,
    const float* hmu_W, const float* hmu_b, const float* cmu_W, const float* cmu_b,
    const float* fc1_W, const float* fc1_b, const float* fc2_W, const float* fc2_b,
    const float* dec_Whh,
    const float* out_W, const float* out_b,
    float* out, int out_size)
{
    extern __shared__ __align__(16) float sm[];
    float* h2b   = sm + O_H;
    float* gsh   = sm + O_GSH;
    float* cfull = sm + O_CF;
    float* pre_sh= sm + O_PRE;
    float* tab_sh= sm + O_TAB;
    float* ow_sh = sm + O_OW;
    float* ob_sh = sm + O_OB;
    float* lsh   = sm + O_LSH;
    float* cat_h = sm + O_CATH;
    float* cat_c = sm + O_CATC;

    const int tid  = threadIdx.x;
    const int w    = tid >> 5;
    const int lane = tid & 31;
    const int s8   = lane & 7;
    const int q    = lane >> 3;
    const int b    = blockIdx.x;
    const int lrA  = w * 8 + q;          // local rows 0..127
    const int lrB  = lrA + 4;
    const int RA   = R_of(lrA, b);
    const int RB   = R_of(lrB, b);

    // ---- recurrent weights (encoder first; decoder reloaded into same regs) ----
    ull wA[16], wB[16];
    load_wrows(enc_Whh, RA, RB, s8, wA, wB);

    // ---- smem prologue loads ----
    for (int i = tid; i < NV * HID / 4; i += TPB)
        ((float4*)ow_sh)[i] = ((const float4*)out_W)[i];
    if (tid < NV) ob_sh[tid] = out_b[tid];
    for (int i = tid; i < ENCL * RPC; i += TPB) {
        int t = i >> 7, lr = i & 127;
        pre_sh[i] = g_pre[t * 1024 + R_of(lr, b)];
    }
    for (int i = tid; i < NV * RPC; i += TPB) {
        int tk = i >> 7, lr = i & 127;
        tab_sh[i] = g_tab[tk * 1024 + R_of(lr, b)];
    }

    // ---- h0 (replicated), c0 slice in warp-0 registers ----
    const int dcid = data_c[0], tcid = target_c[0];
    if (tid < HID) {
        float v = (tid >= HID - 8) ? cond_emb[dcid * 8 + (tid - (HID - 8))] : 0.f;
        h2b[tid] = v;
    }
    float creg = 0.f;
    uint32_t hmap[CS], cmap[CS];
    if (tid < HPC) {
        int j = b * HPC + tid;
        creg = (j >= HID - 8) ? cond_emb[dcid * 8 + (j - (HID - 8))] : 0.f;
        uint32_t hb = smem_u32(h2b), cb = smem_u32(cfull);
#pragma unroll
        for (int r = 0; r < CS; r++) { hmap[r] = mapa_u32(hb, r); cmap[r] = mapa_u32(cb, r); }
    }
    __syncthreads();

    int p = 0;

    // ================= encoder: 16 steps =================
#pragma unroll 1
    for (int t = 0; t < ENCL; t++) {
        float sA, sB;
        dual_dot(h2b + p * HID, s8, wA, wB, sA, sB);
        if (s8 == 0) { gsh[lrA] = sA; gsh[lrB] = sB; }
        __syncthreads();
        if (tid < HPC) {
            const float* pr = pre_sh + t * RPC;
            float g0 = gsh[tid]      + pr[tid];
            float g1 = gsh[32 + tid] + pr[32 + tid];
            float g2 = gsh[64 + tid] + pr[64 + tid];
            float g3 = gsh[96 + tid] + pr[96 + tid];
            float c = sigf(g1) * creg + sigf(g0) * tanhfast(g2);
            float h = sigf(g3) * tanhfast(c);
            creg = c;
            uint32_t off = (uint32_t)(((p ^ 1) * HID + b * HPC + tid) * 4);
#pragma unroll
            for (int r = 0; r < CS; r++) st_cluster_f32(hmap[r] + off, h);
            if (t == ENCL - 1) {
                uint32_t co = (uint32_t)((b * HPC + tid) * 4);
#pragma unroll
                for (int r = 0; r < CS; r++) st_cluster_f32(cmap[r] + co, c);
            }
        }
        cluster_bar();
        p ^= 1;
    }
    // p == 0 here; hT = h2b[0..255], cT = cfull (replicated)

    // ================= latent heads + decoder init (redundant per CTA) =================
    {
        const float4* hv = (const float4*)h2b + lane * 2;
        float4 h0v = hv[0], h1v = hv[1];
        const float4* cv = (const float4*)cfull + lane * 2;
        float4 c0v = cv[0], c1v = cv[1];
#pragma unroll
        for (int half = 0; half < 2; half++) {
            int rr = w + half * 16;
            const float4* pp = (const float4*)(hmu_W + rr * HID);
            float4 a0 = pp[lane * 2], a1 = pp[lane * 2 + 1];
            float s = red32(dot8(a0, a1, h0v, h1v));
            if (lane == 0) cat_h[rr] = s + hmu_b[rr];
            pp = (const float4*)(cmu_W + rr * HID);
            a0 = pp[lane * 2]; a1 = pp[lane * 2 + 1];
            s = red32(dot8(a0, a1, c0v, c1v));
            if (lane == 0) cat_c[rr] = s + cmu_b[rr];
        }
    }
    if (tid < 8) {
        float v = cond_emb[tcid * 8 + tid];
        cat_h[32 + tid] = v; cat_c[32 + tid] = v;
    }
    __syncthreads();
    float newv = 0.f, cnew = 0.f;
    if (tid < HID) {
        float s = fc1_b[tid];
        const float* wr = fc1_W + tid * 40;
#pragma unroll
        for (int k = 0; k < 40; k++) s += cat_h[k] * wr[k];
        newv = s;
    }
    if (tid < HPC) {
        int j = b * HPC + tid;
        float s = fc2_b[j];
        const float* wr = fc2_W + j * 40;
#pragma unroll
        for (int k = 0; k < 40; k++) s += cat_c[k] * wr[k];
        cnew = s;
    }
    __syncthreads();
    if (tid < HID) h2b[tid] = newv;      // p stays 0
    if (tid < HPC) creg = cnew;

    // reload recurrent weights for decoder (same registers)
    load_wrows(dec_Whh, RA, RB, s8, wA, wB);
    __syncthreads();

    // ================= decoder: 25 steps, logits pipelined =================
#pragma unroll 1
    for (int s = 0; s < DECL; s++) {
        const float* hcur = h2b + p * HID;
        // logits_{s-1} from hcur (h after step s-1); concurrent with gate dots
        if (s > 0 && w < 14) {
            const float4* h2 = (const float4*)hcur + lane * 2;
            float4 x0 = h2[0], x1 = h2[1];
#pragma unroll
            for (int half = 0; half < 2; half++) {
                int rr = w + half * 14;
                const float4* pp = (const float4*)(ow_sh + rr * HID) + lane * 2;
                float4 a0 = pp[0], a1 = pp[1];
                float sl = red32(dot8(a0, a1, x0, x1));
                if (lane == 0) lsh[rr] = sl + ob_sh[rr];
            }
        }
        float sA, sB;
        dual_dot(hcur, s8, wA, wB, sA, sB);
        if (s8 == 0) { gsh[lrA] = sA; gsh[lrB] = sB; }
        __syncthreads();
        if (b == 0 && s > 0 && w == 15 && lane < NV)
            out[(s - 1) * NV + lane] = lsh[lane];
        if (tid < HPC) {
            int tok = 0;
            if (s > 0) {
                float v = (tid < NV) ? lsh[tid] : -3.4e38f;
                int idx = tid;
#pragma unroll
                for (int o = 16; o > 0; o >>= 1) {
                    float ov = __shfl_xor_sync(0xffffffffu, v, o);
                    int   oi = __shfl_xor_sync(0xffffffffu, idx, o);
                    if (ov > v || (ov == v && oi < idx)) { v = ov; idx = oi; }
                }
                tok = idx;
                if (tid == 0 && b == 0) out[NV * DECL + (s - 1)] = (float)tok;
            }
            const float* tb = tab_sh + tok * RPC;
            float g0 = gsh[tid]      + tb[tid];
            float g1 = gsh[32 + tid] + tb[32 + tid];
            float g2 = gsh[64 + tid] + tb[64 + tid];
            float g3 = gsh[96 + tid] + tb[96 + tid];
            float c = sigf(g1) * creg + sigf(g0) * tanhfast(g2);
            float h = sigf(g3) * tanhfast(c);
            creg = c;
            uint32_t off = (uint32_t)(((p ^ 1) * HID + b * HPC + tid) * 4);
#pragma unroll
            for (int r = 0; r < CS; r++) st_cluster_f32(hmap[r] + off, h);
        }
        cluster_bar();
        p ^= 1;
    }

    // ---- tail: logits for the last step ----
    {
        const float* hcur = h2b + p * HID;
        if (w < 14) {
            const float4* h2 = (const float4*)hcur + lane * 2;
            float4 x0 = h2[0], x1 = h2[1];
#pragma unroll
            for (int half = 0; half < 2; half++) {
                int rr = w + half * 14;
                const float4* pp = (const float4*)(ow_sh + rr * HID) + lane * 2;
                float4 a0 = pp[0], a1 = pp[1];
                float sl = red32(dot8(a0, a1, x0, x1));
                if (lane == 0) lsh[rr] = sl + ob_sh[rr];
            }
        }
        __syncthreads();
        if (b == 0) {
            if (w == 15 && lane < NV) out[(DECL - 1) * NV + lane] = lsh[lane];
            if (tid < HPC) {
                float v = (tid < NV) ? lsh[tid] : -3.4e38f;
                int idx = tid;
#pragma unroll
                for (int o = 16; o > 0; o >>= 1) {
                    float ov = __shfl_xor_sync(0xffffffffu, v, o);
                    int   oi = __shfl_xor_sync(0xffffffffu, idx, o);
                    if (ov > v || (ov == v && oi < idx)) { v = ov; idx = oi; }
                }
                if (tid == 0) out[NV * DECL + (DECL - 1)] = (float)idx;
            }
        }
    }
    (void)out_size;
}

extern "C" void kernel_launch(void* const* d_in, const int* in_sizes, int n_in,
                              void* d_out, int out_size) {
    (void)in_sizes; (void)n_in;
    const int*   data     = (const int*)  d_in[0];
    const int*   data_c   = (const int*)  d_in[1];
    const int*   target_c = (const int*)  d_in[2];
    const float* cond_emb = (const float*)d_in[3];
    const float* enc_emb  = (const float*)d_in[4];
    const float* enc_Wih  = (const float*)d_in[5];
    const float* enc_Whh  = (const float*)d_in[6];
    const float* enc_bih  = (const float*)d_in[7];
    const float* enc_bhh  = (const float*)d_in[8];
    const float* hmu_W    = (const float*)d_in[9];
    const float* hmu_b    = (const float*)d_in[10];
    const float* cmu_W    = (const float*)d_in[11];
    const float* cmu_b    = (const float*)d_in[12];
    const float* fc1_W    = (const float*)d_in[13];
    const float* fc1_b    = (const float*)d_in[14];
    const float* fc2_W    = (const float*)d_in[15];
    const float* fc2_b    = (const float*)d_in[16];
    const float* dec_emb  = (const float*)d_in[17];
    const float* dec_Wih  = (const float*)d_in[18];
    const float* dec_Whh  = (const float*)d_in[19];
    const float* dec_bih  = (const float*)d_in[20];
    const float* dec_bhh  = (const float*)d_in[21];
    const float* out_W    = (const float*)d_in[22];
    const float* out_b    = (const float*)d_in[23];

    table_kernel<<<256, 256>>>(data, enc_Wih, enc_bih, enc_bhh, enc_emb,
                               dec_Wih, dec_bih, dec_bhh, dec_emb);

    cudaFuncSetAttribute(vae_kernel, cudaFuncAttributeMaxDynamicSharedMemorySize, SMEM_BYTES);
    vae_kernel<<<CS, TPB, SMEM_BYTES>>>(data_c, target_c, cond_emb,
                                        enc_Whh,
                                        hmu_W, hmu_b, cmu_W, cmu_b,
                                        fc1_W, fc1_b, fc2_W, fc2_b,
                                        dec_Whh,
                                        out_W, out_b,
                                        (float*)d_out, out_size);
}